// round 3
// baseline (speedup 1.0000x reference)
#include <cuda_runtime.h>

// SparseAudioModel gather:
//   out[b, s] = sum_e x[b, e, s - time_e],  time_e = idx[b,e]*256, active iff time_e <= s
//
// R3: block spans exactly STEP_SIZE=256 samples (128 threads x float2).
// Since all time_e are multiples of 256, event activity is uniform across the
// whole block: active <=> time_e <= block_start. Compact the active events
// once per block (ballot prefix-sum, order-preserving) into smem as fused
// offsets off_e = e*S - time_e. Inner loop is predicate-free:
//     v = ldcs(base + off);  acc += v;

#define N_SAMPLES 32768
#define N_EVENTS  64
#define STEP_SIZE 256
#define BATCH     16

__global__ __launch_bounds__(128) void sparse_audio_gather(
    const float* __restrict__ x,      // [B, E, S]
    const int*   __restrict__ idx,    // [B, E]
    float*       __restrict__ out)    // [B, S]
{
    __shared__ int s_off[N_EVENTS];   // compacted e*S - time_e, ascending e
    __shared__ int s_cnt[2];

    const int t = threadIdx.x;
    const int b = blockIdx.y;
    const int block_start = blockIdx.x * STEP_SIZE;   // first sample of block

    // ---- compact active events (order-preserving) ----
    bool     act = false;
    unsigned m   = 0;
    int      pos = 0, myoff = 0;
    if (t < N_EVENTS) {
        const int time = idx[b * N_EVENTS + t] * STEP_SIZE;
        act   = (time <= block_start);           // uniform over the block's samples
        m     = __ballot_sync(0xffffffffu, act);
        pos   = __popc(m & ((1u << (t & 31)) - 1));
        myoff = t * N_SAMPLES - time;
        if (t < 32) {                            // warp 0: events 0..31
            if (act) s_off[pos] = myoff;
            if (t == 0) s_cnt[0] = __popc(m);
        }
    }
    __syncthreads();
    if (t >= 32 && t < N_EVENTS) {               // warp 1: events 32..63
        if (act) s_off[s_cnt[0] + pos] = myoff;
        if (t == 32) s_cnt[1] = s_cnt[0] + __popc(m);
    }
    __syncthreads();

    const int n_act = s_cnt[1];

    // ---- predicate-free accumulation ----
    const float* base = x + (size_t)b * N_EVENTS * N_SAMPLES + block_start + t * 2;

    float2 acc = make_float2(0.f, 0.f);

    #pragma unroll 4
    for (int i = 0; i < n_act; ++i) {
        const int off = s_off[i];
        const float2 v = __ldcs(reinterpret_cast<const float2*>(base + off));
        acc.x += v.x;
        acc.y += v.y;
    }

    *reinterpret_cast<float2*>(out + (size_t)b * N_SAMPLES + block_start + t * 2) = acc;
}

extern "C" void kernel_launch(void* const* d_in, const int* in_sizes, int n_in,
                              void* d_out, int out_size)
{
    const float* x   = (const float*)d_in[0];   // [16, 64, 32768] float32
    const int*   idx = (const int*)  d_in[1];   // [16, 64] int32
    float*       out = (float*)d_out;           // [16, 1, 32768] float32

    dim3 block(128);
    dim3 grid(N_SAMPLES / STEP_SIZE, BATCH);    // (128, 16) = 2048 blocks
    sparse_audio_gather<<<grid, block>>>(x, idx, out);
}

// round 4
// speedup vs baseline: 1.4300x; 1.4300x over previous
#include <cuda_runtime.h>

// SparseAudioModel gather:
//   out[b, s] = sum_e x[b, e, s - time_e],  time_e = idx[b,e]*256, active iff time_e <= s
//
// R4 vs R2:
//  - heavy-first 1-D grid: per-block work is ~linear in block_start (1..64
//    active events); issuing high-s blocks first lets the near-empty low-s
//    blocks backfill the final wave instead of a fat 64-load straggler tail.
//  - branch-free inner loop: predicated ld.global.cs via inline PTX (no
//    BSSY/BSYNC per iteration; ptxas can front-batch loads for high MLP).
//  - .cs streaming loads/stores: data is touched exactly once (128 MB read-
//    once working set >> L2), keep L2 out of the way.

#define N_SAMPLES 32768
#define N_EVENTS  64
#define STEP_SIZE 256
#define BATCH     16
#define TILE      512                 // samples per block: 256 thr * float2

__global__ __launch_bounds__(256) void sparse_audio_gather(
    const float* __restrict__ x,      // [B, E, S]
    const int*   __restrict__ idx,    // [B, E]
    float*       __restrict__ out)    // [B, S]
{
    __shared__ int s_time[N_EVENTS];

    const int bid = blockIdx.x;
    const int b   = bid & (BATCH - 1);
    // heavy blocks (large block_start => most active events) run first
    const int block_start = ((N_SAMPLES / TILE - 1) - (bid >> 4)) * TILE;

    const int t = threadIdx.x;
    if (t < N_EVENTS)
        s_time[t] = idx[b * N_EVENTS + t] * STEP_SIZE;
    __syncthreads();

    const int s2 = block_start + t * 2;           // this thread's 2 samples
    const float* xb = x + (size_t)b * N_EVENTS * N_SAMPLES + s2;

    float accx = 0.f, accy = 0.f;

    #pragma unroll
    for (int e = 0; e < N_EVENTS; ++e) {
        const int time = s_time[e];
        const float* p = xb + ((size_t)e * N_SAMPLES - time);
        float vx = 0.f, vy = 0.f;
        // predicated vector load, no branch: inactive lanes keep 0
        asm("{\n\t"
            ".reg .pred p;\n\t"
            "setp.le.s32 p, %2, %3;\n\t"
            "@p ld.global.cs.v2.f32 {%0, %1}, [%4];\n\t"
            "}"
            : "+f"(vx), "+f"(vy)
            : "r"(time), "r"(s2), "l"(p));
        accx += vx;
        accy += vy;
    }

    float2 r = make_float2(accx, accy);
    asm("st.global.cs.v2.f32 [%0], {%1, %2};"
        :: "l"(out + (size_t)b * N_SAMPLES + s2), "f"(r.x), "f"(r.y)
        : "memory");
}

extern "C" void kernel_launch(void* const* d_in, const int* in_sizes, int n_in,
                              void* d_out, int out_size)
{
    const float* x   = (const float*)d_in[0];   // [16, 64, 32768] float32
    const int*   idx = (const int*)  d_in[1];   // [16, 64] int32
    float*       out = (float*)d_out;           // [16, 1, 32768] float32

    dim3 block(256);
    dim3 grid((N_SAMPLES / TILE) * BATCH);      // 64 * 16 = 1024 blocks, 1-D
    sparse_audio_gather<<<grid, block>>>(x, idx, out);
}

// round 5
// speedup vs baseline: 1.4550x; 1.0175x over previous
#include <cuda_runtime.h>

// SparseAudioModel gather:
//   out[b, s] = sum_e x[b, e, s - time_e],  time_e = idx[b,e]*256, active iff time_e <= s
//
// R5 vs R4:
//  - mirror-pair tiles: block handles tile k AND tile 127-k (256 samples each),
//    so per-block load count is ~uniform (~65) instead of 1..64 -> perfect
//    SM-level balance with all 1024 blocks co-resident.
//  - software-pipelined batches: 8 events x 2 tiles = 16 predicated loads
//    issued into register arrays BEFORE accumulation, forcing ptxas to keep a
//    deep load batch in flight (R4's 32-reg schedule exposed DRAM latency).

#define N_SAMPLES 32768
#define N_EVENTS  64
#define STEP_SIZE 256
#define BATCH     16
#define TILE      256                 // one tile = 128 threads * float2
#define NTILES    (N_SAMPLES / TILE)  // 128
#define GRP       8

__global__ __launch_bounds__(128) void sparse_audio_gather(
    const float* __restrict__ x,      // [B, E, S]
    const int*   __restrict__ idx,    // [B, E]
    float*       __restrict__ out)    // [B, S]
{
    __shared__ int s_time[N_EVENTS];

    const int k = blockIdx.x;         // tile pair id 0..63
    const int b = blockIdx.y;
    const int t = threadIdx.x;

    if (t < N_EVENTS)
        s_time[t] = idx[b * N_EVENTS + t] * STEP_SIZE;
    __syncthreads();

    const int s_lo = k * TILE + t * 2;                 // light tile
    const int s_hi = (NTILES - 1 - k) * TILE + t * 2;  // heavy tile

    const float* xb = x + (size_t)b * N_EVENTS * N_SAMPLES;

    float alx = 0.f, aly = 0.f;       // lo-tile accumulator
    float ahx = 0.f, ahy = 0.f;       // hi-tile accumulator

    #pragma unroll
    for (int g = 0; g < N_EVENTS; g += GRP) {
        float vlx[GRP], vly[GRP], vhx[GRP], vhy[GRP];

        // ---- issue 16 predicated loads, no consumption yet ----
        #pragma unroll
        for (int j = 0; j < GRP; ++j) {
            const int e    = g + j;
            const int time = s_time[e];
            const float* pe = xb + (size_t)e * N_SAMPLES - time;

            vlx[j] = 0.f; vly[j] = 0.f;
            vhx[j] = 0.f; vhy[j] = 0.f;

            asm("{\n\t"
                ".reg .pred p;\n\t"
                "setp.le.s32 p, %2, %3;\n\t"
                "@p ld.global.cs.v2.f32 {%0, %1}, [%4];\n\t"
                "}"
                : "+f"(vlx[j]), "+f"(vly[j])
                : "r"(time), "r"(s_lo), "l"(pe + s_lo));

            asm("{\n\t"
                ".reg .pred p;\n\t"
                "setp.le.s32 p, %2, %3;\n\t"
                "@p ld.global.cs.v2.f32 {%0, %1}, [%4];\n\t"
                "}"
                : "+f"(vhx[j]), "+f"(vhy[j])
                : "r"(time), "r"(s_hi), "l"(pe + s_hi));
        }

        // ---- consume ----
        #pragma unroll
        for (int j = 0; j < GRP; ++j) {
            alx += vlx[j]; aly += vly[j];
            ahx += vhx[j]; ahy += vhy[j];
        }
    }

    float* ob = out + (size_t)b * N_SAMPLES;
    asm("st.global.cs.v2.f32 [%0], {%1, %2};"
        :: "l"(ob + s_lo), "f"(alx), "f"(aly) : "memory");
    asm("st.global.cs.v2.f32 [%0], {%1, %2};"
        :: "l"(ob + s_hi), "f"(ahx), "f"(ahy) : "memory");
}

extern "C" void kernel_launch(void* const* d_in, const int* in_sizes, int n_in,
                              void* d_out, int out_size)
{
    const float* x   = (const float*)d_in[0];   // [16, 64, 32768] float32
    const int*   idx = (const int*)  d_in[1];   // [16, 64] int32
    float*       out = (float*)d_out;           // [16, 1, 32768] float32

    dim3 block(128);
    dim3 grid(NTILES / 2, BATCH);               // (64, 16) = 1024 blocks
    sparse_audio_gather<<<grid, block>>>(x, idx, out);
}